// round 1
// baseline (speedup 1.0000x reference)
#include <cuda_runtime.h>

// AllZeroDigitalFilter: out[b, n*P+p] = sum_k x[b, n*P+p-k] * (h[b,n,k] + (p/P)*(h[b,n+1,k]-h[b,n,k]))
// B=8, N=800, P=80, taps=M+1=256, T=N*P=64000. h[b,N] clamps to h[b,N-1].

#define TAPS 256
#define MM   255
#define PP   80
#define SEG  8                    // segments per block
#define OUTB (SEG * PP)           // 640 outputs per block
#define RR   4                    // outputs per thread (consecutive)
#define NTHREADS (OUTB / RR)      // 160 threads (5 warps)
#define FSTRIDE (2 * TAPS + 8)    // 520 floats per segment (h0 | d), +8 pad kills bank aliasing
#define NB 800
#define BB 8
#define TT (NB * PP)              // 64000

__global__ __launch_bounds__(NTHREADS)
void azdf_kernel(const float* __restrict__ x,
                 const float* __restrict__ h,
                 float* __restrict__ out)
{
    __shared__ float sf[SEG * FSTRIDE];        // filters: h0 and d=h1-h0 per segment
    __shared__ float sx[8 + TAPS + OUTB];      // 8-float front pad + 896-value x window

    const int tid = threadIdx.x;
    const int b   = blockIdx.y;
    const int n0  = blockIdx.x * SEG;

    // ---- stage filters: for each of SEG segments load h[n] and h[min(n+1,N-1)]-h[n]
    {
        const float4* hb = (const float4*)(h + (size_t)b * NB * TAPS);
        for (int idx = tid; idx < SEG * (TAPS / 4); idx += NTHREADS) {
            int s  = idx >> 6;          // segment
            int k4 = idx & 63;          // float4 index within row
            int n  = n0 + s;
            int nn = (n + 1 < NB) ? (n + 1) : (NB - 1);
            float4 a = hb[n  * (TAPS / 4) + k4];
            float4 c = hb[nn * (TAPS / 4) + k4];
            float* f0 = sf + s * FSTRIDE;
            float* f1 = f0 + TAPS;
            f0[k4 * 4 + 0] = a.x; f0[k4 * 4 + 1] = a.y;
            f0[k4 * 4 + 2] = a.z; f0[k4 * 4 + 3] = a.w;
            f1[k4 * 4 + 0] = c.x - a.x; f1[k4 * 4 + 1] = c.y - a.y;
            f1[k4 * 4 + 2] = c.z - a.z; f1[k4 * 4 + 3] = c.w - a.w;
        }
    }
    // ---- stage x window: global indices [n0*P - M, n0*P - M + 895], zero-pad OOB
    {
        const float* xb = x + (size_t)b * TT;
        const int gbase = n0 * PP - MM;
        for (int j = tid; j < TAPS + OUTB; j += NTHREADS) {
            int g = gbase + j;
            sx[8 + j] = (g >= 0 && g < TT) ? xb[g] : 0.0f;
        }
        if (tid < 8) sx[tid] = 0.0f;   // front pad (only the dead final prefetch touches it)
    }
    __syncthreads();

    const int pout = tid * RR;                  // first output of this thread within block
    const int s    = tid / (PP / RR);           // segment = tid/20 (RR divides P)
    const float* f0  = sf + s * FSTRIDE;
    const float* f1  = f0 + TAPS;
    const float* sxo = sx + 8;

    float a00 = 0.f, a01 = 0.f, a02 = 0.f, a03 = 0.f;   // conv with h0
    float a10 = 0.f, a11 = 0.f, a12 = 0.f, a13 = 0.f;   // conv with d

    // sliding 8-float register window: W[i] = sxo[pout + 252 - 4*kk + i]
    // output r at tap k=4*kk+u uses W[3 - u + r]
    float W0, W1, W2, W3, W4, W5, W6, W7;
    {
        float4 w0 = *(const float4*)(sxo + pout + 252);
        float4 w1 = *(const float4*)(sxo + pout + 256);
        W0 = w0.x; W1 = w0.y; W2 = w0.z; W3 = w0.w;
        W4 = w1.x; W5 = w1.y; W6 = w1.z; W7 = w1.w;
    }

    #pragma unroll 4
    for (int kk = 0; kk < TAPS / 4; kk++) {
        float4 c0 = *(const float4*)(f0 + kk * 4);
        float4 c1 = *(const float4*)(f1 + kk * 4);

        // u = 0 (k = 4kk+0): x = W[3+r]
        a00 += W3 * c0.x; a01 += W4 * c0.x; a02 += W5 * c0.x; a03 += W6 * c0.x;
        a10 += W3 * c1.x; a11 += W4 * c1.x; a12 += W5 * c1.x; a13 += W6 * c1.x;
        // u = 1: x = W[2+r]
        a00 += W2 * c0.y; a01 += W3 * c0.y; a02 += W4 * c0.y; a03 += W5 * c0.y;
        a10 += W2 * c1.y; a11 += W3 * c1.y; a12 += W4 * c1.y; a13 += W5 * c1.y;
        // u = 2: x = W[1+r]
        a00 += W1 * c0.z; a01 += W2 * c0.z; a02 += W3 * c0.z; a03 += W4 * c0.z;
        a10 += W1 * c1.z; a11 += W2 * c1.z; a12 += W3 * c1.z; a13 += W4 * c1.z;
        // u = 3: x = W[0+r]
        a00 += W0 * c0.w; a01 += W1 * c0.w; a02 += W2 * c0.w; a03 += W3 * c0.w;
        a10 += W0 * c1.w; a11 += W1 * c1.w; a12 += W2 * c1.w; a13 += W3 * c1.w;

        // slide window down by 4 (final iteration's load is dead but lands in the pad)
        float4 nw = *(const float4*)(sxo + pout + 248 - 4 * kk);
        W4 = W0; W5 = W1; W6 = W2; W7 = W3;
        W0 = nw.x; W1 = nw.y; W2 = nw.z; W3 = nw.w;
    }

    // blend: out = y0 + (p/P) * y1
    const float pb = (float)(pout % PP);
    const float inv = 1.0f / (float)PP;
    float4 o;
    o.x = a00 + (pb + 0.0f) * inv * a10;
    o.y = a01 + (pb + 1.0f) * inv * a11;
    o.z = a02 + (pb + 2.0f) * inv * a12;
    o.w = a03 + (pb + 3.0f) * inv * a13;
    *(float4*)(out + (size_t)b * TT + n0 * PP + pout) = o;
}

extern "C" void kernel_launch(void* const* d_in, const int* in_sizes, int n_in,
                              void* d_out, int out_size)
{
    const float* x = (const float*)d_in[0];
    const float* h = (const float*)d_in[1];
    float* out = (float*)d_out;
    (void)in_sizes; (void)n_in; (void)out_size;

    dim3 grid(NB / SEG, BB);   // 100 x 8 = 800 blocks
    azdf_kernel<<<grid, NTHREADS>>>(x, h, out);
}